// round 15
// baseline (speedup 1.0000x reference)
#include <cuda_runtime.h>

#define SDIM   128
#define VDIM   352           // 64*3 + 32*5
#define DIM    480
#define RPB    4             // rows per block
#define NTHR   128
#define NVTOT  (RPB * 88)    // 352 float4 in vector region
#define EPS    1e-5f

__device__ __forceinline__ float4 ldcs_f4(const float4* p) {
    float4 v;
    asm volatile("ld.global.cs.v4.f32 {%0,%1,%2,%3}, [%4];"
                 : "=f"(v.x), "=f"(v.y), "=f"(v.z), "=f"(v.w) : "l"(p));
    return v;
}
__device__ __forceinline__ void stcs_f4(float4* p, float4 v) {
    asm volatile("st.global.cs.v4.f32 [%0], {%1,%2,%3,%4};"
                 :: "l"(p), "f"(v.x), "f"(v.y), "f"(v.z), "f"(v.w));
}

__global__ __launch_bounds__(NTHR) void eln_kernel(
    const float* __restrict__ x,
    const float* __restrict__ weight,
    const float* __restrict__ bias,
    float* __restrict__ out)
{
    __shared__ float vec[RPB][VDIM];   // 5.6 KB

    const int tid  = threadIdx.x;
    const int lane = tid & 31;
    const int wrp  = tid >> 5;
    const long long row0 = (long long)blockIdx.x * RPB;

    // ---- front-batch ALL loads ----
    const float4 w4 = __ldg((const float4*)weight + lane);
    const float4 b4 = __ldg((const float4*)bias   + lane);

    // warp w owns row (row0+w)'s scalar region: 32 x LDG.128
    const float4 sv = ldcs_f4((const float4*)(x + (row0 + wrp) * DIM) + lane);

    // vector region: 4 rows x 88 float4 = 352, strided by 128 threads
    float4 v[3];
    #pragma unroll
    for (int k = 0; k < 3; k++) {
        int idx = tid + NTHR * k;
        if (idx < NVTOT) {
            int r = idx / 88, j = idx - r * 88;
            v[k] = ldcs_f4((const float4*)(x + (row0 + r) * DIM + SDIM) + j);
        }
    }

    // ---- scalar layernorm: warp-local, no barrier ----
    float sum = sv.x + sv.y + sv.z + sv.w;
    float sq  = sv.x * sv.x + sv.y * sv.y + sv.z * sv.z + sv.w * sv.w;
    #pragma unroll
    for (int o = 16; o; o >>= 1) {
        sum += __shfl_xor_sync(0xFFFFFFFFu, sum, o);
        sq  += __shfl_xor_sync(0xFFFFFFFFu, sq,  o);
    }
    const float m  = sum * (1.0f / 128.0f);
    const float rs = rsqrtf(sq * (1.0f / 128.0f) - m * m + EPS);
    float4 so;
    so.x = (sv.x - m) * rs * w4.x + b4.x;
    so.y = (sv.y - m) * rs * w4.y + b4.y;
    so.z = (sv.z - m) * rs * w4.z + b4.z;
    so.w = (sv.w - m) * rs * w4.w + b4.w;
    stcs_f4((float4*)(out + (row0 + wrp) * DIM) + lane, so);

    // ---- stage vector region into smem (conflict-free STS.128) ----
    #pragma unroll
    for (int k = 0; k < 3; k++) {
        int idx = tid + NTHR * k;
        if (idx < NVTOT) ((float4*)vec)[idx] = v[k];
    }
    __syncthreads();   // the ONLY barrier

    // ---- bundled segment epilogue: 4 consecutive segments per thread,
    //      aligned LDS.128 reads + pure STG.128 writes ----
    if (tid < 64) {
        // seg3 bundle: row r, segments 4b..4b+3, floats 12b..12b+11
        const int r = tid >> 4, b = tid & 15;
        const float4* p4 = (const float4*)&vec[r][12 * b];   // 48b bytes: aligned
        float4 A = p4[0], B = p4[1], C = p4[2];
        // groups: (A.x A.y A.z) (A.w B.x B.y) (B.z B.w C.x) (C.y C.z C.w)
        float m0 = (A.x + A.y + A.z) * (1.0f / 3.0f);
        float m1 = (A.w + B.x + B.y) * (1.0f / 3.0f);
        float m2 = (B.z + B.w + C.x) * (1.0f / 3.0f);
        float m3 = (C.y + C.z + C.w) * (1.0f / 3.0f);
        float d00 = A.x - m0, d01 = A.y - m0, d02 = A.z - m0;
        float d10 = A.w - m1, d11 = B.x - m1, d12 = B.y - m1;
        float d20 = B.z - m2, d21 = B.w - m2, d22 = C.x - m2;
        float d30 = C.y - m3, d31 = C.z - m3, d32 = C.w - m3;
        float r0 = rsqrtf((d00*d00 + d01*d01 + d02*d02) * (1.0f/3.0f) + EPS);
        float r1 = rsqrtf((d10*d10 + d11*d11 + d12*d12) * (1.0f/3.0f) + EPS);
        float r2 = rsqrtf((d20*d20 + d21*d21 + d22*d22) * (1.0f/3.0f) + EPS);
        float r3 = rsqrtf((d30*d30 + d31*d31 + d32*d32) * (1.0f/3.0f) + EPS);
        float4* q = (float4*)(out + (row0 + r) * DIM + SDIM + 12 * b);
        stcs_f4(q + 0, make_float4(d00*r0, d01*r0, d02*r0, d10*r1));
        stcs_f4(q + 1, make_float4(d11*r1, d12*r1, d20*r2, d21*r2));
        stcs_f4(q + 2, make_float4(d22*r2, d30*r3, d31*r3, d32*r3));
    } else if (tid < 96) {
        // seg5 bundle: row r, segments 4b..4b+3, floats 192+20b..+19
        const int u = tid - 64;
        const int r = u >> 3, b = u & 7;
        const float4* p4 = (const float4*)&vec[r][192 + 20 * b];  // 768+80b: aligned
        float4 A = p4[0], B = p4[1], C = p4[2], D = p4[3], E = p4[4];
        // groups of 5: (A.x..B.x) (B.y..C.y) (C.z..D.z) (D.w..E.w)
        float m0 = (A.x + A.y + A.z + A.w + B.x) * 0.2f;
        float m1 = (B.y + B.z + B.w + C.x + C.y) * 0.2f;
        float m2 = (C.z + C.w + D.x + D.y + D.z) * 0.2f;
        float m3 = (D.w + E.x + E.y + E.z + E.w) * 0.2f;
        float d00 = A.x-m0, d01 = A.y-m0, d02 = A.z-m0, d03 = A.w-m0, d04 = B.x-m0;
        float d10 = B.y-m1, d11 = B.z-m1, d12 = B.w-m1, d13 = C.x-m1, d14 = C.y-m1;
        float d20 = C.z-m2, d21 = C.w-m2, d22 = D.x-m2, d23 = D.y-m2, d24 = D.z-m2;
        float d30 = D.w-m3, d31 = E.x-m3, d32 = E.y-m3, d33 = E.z-m3, d34 = E.w-m3;
        float r0 = rsqrtf((d00*d00 + d01*d01 + d02*d02 + d03*d03 + d04*d04) * 0.2f + EPS);
        float r1 = rsqrtf((d10*d10 + d11*d11 + d12*d12 + d13*d13 + d14*d14) * 0.2f + EPS);
        float r2 = rsqrtf((d20*d20 + d21*d21 + d22*d22 + d23*d23 + d24*d24) * 0.2f + EPS);
        float r3 = rsqrtf((d30*d30 + d31*d31 + d32*d32 + d33*d33 + d34*d34) * 0.2f + EPS);
        float4* q = (float4*)(out + (row0 + r) * DIM + SDIM + 192 + 20 * b);
        stcs_f4(q + 0, make_float4(d00*r0, d01*r0, d02*r0, d03*r0));
        stcs_f4(q + 1, make_float4(d04*r0, d10*r1, d11*r1, d12*r1));
        stcs_f4(q + 2, make_float4(d13*r1, d14*r1, d20*r2, d21*r2));
        stcs_f4(q + 3, make_float4(d22*r2, d23*r2, d24*r2, d30*r3));
        stcs_f4(q + 4, make_float4(d31*r3, d32*r3, d33*r3, d34*r3));
    }
}

extern "C" void kernel_launch(void* const* d_in, const int* in_sizes, int n_in,
                              void* d_out, int out_size)
{
    const float* x      = (const float*)d_in[0];
    const float* weight = (const float*)d_in[1];
    const float* bias   = (const float*)d_in[2];
    float* out = (float*)d_out;

    const int n_rows = in_sizes[0] / DIM;   // 262144
    eln_kernel<<<n_rows / RPB, NTHR>>>(x, weight, bias, out);
}

// round 16
// speedup vs baseline: 1.0112x; 1.0112x over previous
#include <cuda_runtime.h>

#define SDIM   128
#define VDIM   352           // 64*3 + 32*5
#define DIM    480
#define RPB    4             // rows per block
#define NTHR   128
#define NVTOT  (RPB * 88)    // 352 float4 in vector region
#define EPS    1e-5f

__device__ __forceinline__ float4 ldcs_f4(const float4* p) {
    float4 v;
    asm volatile("ld.global.cs.v4.f32 {%0,%1,%2,%3}, [%4];"
                 : "=f"(v.x), "=f"(v.y), "=f"(v.z), "=f"(v.w) : "l"(p));
    return v;
}
__device__ __forceinline__ void stcs_f4(float4* p, float4 v) {
    asm volatile("st.global.cs.v4.f32 [%0], {%1,%2,%3,%4};"
                 :: "l"(p), "f"(v.x), "f"(v.y), "f"(v.z), "f"(v.w));
}
__device__ __forceinline__ void stcs_f(float* p, float v) {
    asm volatile("st.global.cs.f32 [%0], %1;" :: "l"(p), "f"(v));
}

__global__ __launch_bounds__(NTHR) void eln_kernel(
    const float* __restrict__ x,
    const float* __restrict__ weight,
    const float* __restrict__ bias,
    float* __restrict__ out)
{
    __shared__ float vec[RPB][VDIM];   // 5.6 KB

    const int tid  = threadIdx.x;
    const int lane = tid & 31;
    const int wrp  = tid >> 5;
    const long long row0 = (long long)blockIdx.x * RPB;

    // ---- front-batch ALL loads ----
    const float4 w4 = __ldg((const float4*)weight + lane);
    const float4 b4 = __ldg((const float4*)bias   + lane);

    // warp w owns row (row0+w)'s scalar region: 32 x LDG.128
    const float4 sv = ldcs_f4((const float4*)(x + (row0 + wrp) * DIM) + lane);

    // vector region: 4 rows x 88 float4 = 352, strided by 128 threads
    float4 v[3];
    #pragma unroll
    for (int k = 0; k < 3; k++) {
        int idx = tid + NTHR * k;
        if (idx < NVTOT) {
            int r = idx / 88, j = idx - r * 88;
            v[k] = ldcs_f4((const float4*)(x + (row0 + r) * DIM + SDIM) + j);
        }
    }

    // ---- scalar layernorm: warp-local, no barrier ----
    float sum = sv.x + sv.y + sv.z + sv.w;
    float sq  = sv.x * sv.x + sv.y * sv.y + sv.z * sv.z + sv.w * sv.w;
    #pragma unroll
    for (int o = 16; o; o >>= 1) {
        sum += __shfl_xor_sync(0xFFFFFFFFu, sum, o);
        sq  += __shfl_xor_sync(0xFFFFFFFFu, sq,  o);
    }
    const float m  = sum * (1.0f / 128.0f);
    const float rs = rsqrtf(sq * (1.0f / 128.0f) - m * m + EPS);
    float4 so;
    so.x = (sv.x - m) * rs * w4.x + b4.x;
    so.y = (sv.y - m) * rs * w4.y + b4.y;
    so.z = (sv.z - m) * rs * w4.z + b4.z;
    so.w = (sv.w - m) * rs * w4.w + b4.w;
    stcs_f4((float4*)(out + (row0 + wrp) * DIM) + lane, so);

    // ---- stage vector region into smem (conflict-free STS.128) ----
    #pragma unroll
    for (int k = 0; k < 3; k++) {
        int idx = tid + NTHR * k;
        if (idx < NVTOT) ((float4*)vec)[idx] = v[k];
    }
    __syncthreads();   // the ONLY barrier

    // ---- segment norms: read smem strided, normalize in regs,
    //      store DIRECTLY to global (coalesced strided STG.32) ----
    #pragma unroll
    for (int k = 0; k < 3; k++) {
        int s = tid + NTHR * k;           // 0..383
        int r = s / 96, k96 = s - r * 96;
        float* og = out + (row0 + r) * DIM + SDIM;
        if (k96 < 64) {
            const float* p = &vec[r][3 * k96];
            float a = p[0], b = p[1], c = p[2];
            float sm = (a + b + c) * (1.0f / 3.0f);
            float da = a - sm, db = b - sm, dc = c - sm;
            float rr = rsqrtf((da * da + db * db + dc * dc) * (1.0f / 3.0f) + EPS);
            float* q = og + 3 * k96;
            stcs_f(q + 0, da * rr);
            stcs_f(q + 1, db * rr);
            stcs_f(q + 2, dc * rr);
        } else {
            const float* p = &vec[r][192 + 5 * (k96 - 64)];
            float a = p[0], b = p[1], c = p[2], d = p[3], e = p[4];
            float sm = (a + b + c + d + e) * 0.2f;
            float da = a - sm, db = b - sm, dc = c - sm, dd = d - sm, de = e - sm;
            float rr = rsqrtf((da * da + db * db + dc * dc + dd * dd + de * de) * 0.2f + EPS);
            float* q = og + 192 + 5 * (k96 - 64);
            stcs_f(q + 0, da * rr);
            stcs_f(q + 1, db * rr);
            stcs_f(q + 2, dc * rr);
            stcs_f(q + 3, dd * rr);
            stcs_f(q + 4, de * rr);
        }
    }
}

extern "C" void kernel_launch(void* const* d_in, const int* in_sizes, int n_in,
                              void* d_out, int out_size)
{
    const float* x      = (const float*)d_in[0];
    const float* weight = (const float*)d_in[1];
    const float* bias   = (const float*)d_in[2];
    float* out = (float*)d_out;

    const int n_rows = in_sizes[0] / DIM;   // 262144
    eln_kernel<<<n_rows / RPB, NTHR>>>(x, weight, bias, out);
}